// round 1
// baseline (speedup 1.0000x reference)
#include <cuda_runtime.h>
#include <math.h>

#define BS    2
#define SEQ   2048
#define DEMB  1024
#define DATTN 1024
#define NH    16
#define HD    64
#define MROWS (BS*SEQ)   // 4096

#define LOG2E 1.4426950408889634f

// Scratch (device globals -- no allocation allowed in kernel_launch)
__device__ float g_q[MROWS * DATTN];
__device__ float g_k[MROWS * DATTN];
__device__ float g_v[MROWS * DATTN];
__device__ float g_ctx[MROWS * DATTN];

// ---------------------------------------------------------------------------
// C[m,n] = sum_k A[m,k] * B[n,k]  (+ bias[n] if bias != nullptr)
// A: MxK row-major, B: NxK row-major ("NT" gemm, torch Linear layout)
// Block tile 128x128, K-tile 8, 256 threads, 8x8 per-thread micro-tile.
// ---------------------------------------------------------------------------
__global__ __launch_bounds__(256) void sgemm_nt(const float* __restrict__ A,
                                                const float* __restrict__ B,
                                                const float* __restrict__ bias,
                                                float* __restrict__ C,
                                                int M, int N, int K)
{
    __shared__ float As[8][128];
    __shared__ float Bs[8][128];

    const int tid = threadIdx.x;
    const int tx  = tid & 15;        // 0..15 -> n micro
    const int ty  = tid >> 4;        // 0..15 -> m micro
    const int m0  = blockIdx.y * 128;
    const int n0  = blockIdx.x * 128;

    const int lrow = tid >> 1;       // 0..127
    const int lk   = (tid & 1) * 4;  // 0 or 4

    const float* Ap = A + (size_t)(m0 + lrow) * K + lk;
    const float* Bp = B + (size_t)(n0 + lrow) * K + lk;

    float acc[8][8];
#pragma unroll
    for (int i = 0; i < 8; i++)
#pragma unroll
        for (int j = 0; j < 8; j++) acc[i][j] = 0.0f;

    for (int k0 = 0; k0 < K; k0 += 8) {
        float4 av = *(const float4*)(Ap + k0);
        float4 bv = *(const float4*)(Bp + k0);
        As[lk + 0][lrow] = av.x; As[lk + 1][lrow] = av.y;
        As[lk + 2][lrow] = av.z; As[lk + 3][lrow] = av.w;
        Bs[lk + 0][lrow] = bv.x; Bs[lk + 1][lrow] = bv.y;
        Bs[lk + 2][lrow] = bv.z; Bs[lk + 3][lrow] = bv.w;
        __syncthreads();

#pragma unroll
        for (int kk = 0; kk < 8; kk++) {
            float4 a0 = *(const float4*)&As[kk][ty * 8];
            float4 a1 = *(const float4*)&As[kk][ty * 8 + 4];
            float4 b0 = *(const float4*)&Bs[kk][tx * 8];
            float4 b1 = *(const float4*)&Bs[kk][tx * 8 + 4];
            float a[8] = {a0.x, a0.y, a0.z, a0.w, a1.x, a1.y, a1.z, a1.w};
            float b[8] = {b0.x, b0.y, b0.z, b0.w, b1.x, b1.y, b1.z, b1.w};
#pragma unroll
            for (int i = 0; i < 8; i++)
#pragma unroll
                for (int j = 0; j < 8; j++)
                    acc[i][j] += a[i] * b[j];
        }
        __syncthreads();
    }

#pragma unroll
    for (int i = 0; i < 8; i++) {
        int m = m0 + ty * 8 + i;
#pragma unroll
        for (int j = 0; j < 8; j++) {
            int n = n0 + tx * 8 + j;
            float v = acc[i][j];
            if (bias) v += bias[n];
            C[(size_t)m * N + n] = v;
        }
    }
}

// ---------------------------------------------------------------------------
// Causal flash attention, fp32. One block per (q-tile of 64 rows, head, batch)
// Br = Bc = 64, D = 64. Online softmax. 256 threads; per-thread 4x4 S and O.
// Q/K/V layout: [b*SEQ + s, h*64 + d] (row-major 4096 x 1024).
// ---------------------------------------------------------------------------
#define BR   64
#define BC   64
#define SSTR 65   // padded smem stride

extern __shared__ float sm_att[];

__global__ __launch_bounds__(256) void attn_kernel(const float* __restrict__ Q,
                                                   const float* __restrict__ K,
                                                   const float* __restrict__ V,
                                                   float* __restrict__ CTX)
{
    float* Qs = sm_att;
    float* Ks = Qs + BR * SSTR;
    float* Vs = Ks + BC * SSTR;
    float* Ps = Vs + BC * SSTR;

    const int qt = blockIdx.x;   // 0..31
    const int h  = blockIdx.y;   // 0..15
    const int b  = blockIdx.z;   // 0..1

    const int tid = threadIdx.x;
    const int tx  = tid & 15;    // col micro
    const int ty  = tid >> 4;    // row micro

    const float* Qh = Q + (size_t)b * SEQ * DATTN + h * HD;
    const float* Kh = K + (size_t)b * SEQ * DATTN + h * HD;
    const float* Vh = V + (size_t)b * SEQ * DATTN + h * HD;

    // Load Q tile (64 rows x 64 d), 4096 floats = 1024 float4 / 256 threads
#pragma unroll
    for (int it = 0; it < 4; it++) {
        int idx = it * 256 + tid;       // 0..1023
        int r   = idx >> 4;             // 0..63
        int c4  = (idx & 15) * 4;
        float4 v = *(const float4*)(Qh + (size_t)(qt * BR + r) * DATTN + c4);
        Qs[r * SSTR + c4 + 0] = v.x;
        Qs[r * SSTR + c4 + 1] = v.y;
        Qs[r * SSTR + c4 + 2] = v.z;
        Qs[r * SSTR + c4 + 3] = v.w;
    }

    float m_i[4], l_i[4], o[4][4];
#pragma unroll
    for (int i = 0; i < 4; i++) {
        m_i[i] = -1e30f;
        l_i[i] = 0.0f;
#pragma unroll
        for (int j = 0; j < 4; j++) o[i][j] = 0.0f;
    }

    for (int t = 0; t <= qt; t++) {
        __syncthreads();  // protect Ks/Vs/Ps from previous iteration readers

        // Load K and V tiles (each 64x64)
#pragma unroll
        for (int it = 0; it < 4; it++) {
            int idx = it * 256 + tid;
            int r   = idx >> 4;
            int c4  = (idx & 15) * 4;
            float4 kv = *(const float4*)(Kh + (size_t)(t * BC + r) * DATTN + c4);
            Ks[r * SSTR + c4 + 0] = kv.x;
            Ks[r * SSTR + c4 + 1] = kv.y;
            Ks[r * SSTR + c4 + 2] = kv.z;
            Ks[r * SSTR + c4 + 3] = kv.w;
            float4 vv = *(const float4*)(Vh + (size_t)(t * BC + r) * DATTN + c4);
            Vs[r * SSTR + c4 + 0] = vv.x;
            Vs[r * SSTR + c4 + 1] = vv.y;
            Vs[r * SSTR + c4 + 2] = vv.z;
            Vs[r * SSTR + c4 + 3] = vv.w;
        }
        __syncthreads();

        // S = Q K^T  (per-thread 4x4)
        float s[4][4];
#pragma unroll
        for (int i = 0; i < 4; i++)
#pragma unroll
            for (int j = 0; j < 4; j++) s[i][j] = 0.0f;

#pragma unroll 8
        for (int d = 0; d < HD; d++) {
            float a[4], bb[4];
#pragma unroll
            for (int i = 0; i < 4; i++) a[i]  = Qs[(ty * 4 + i) * SSTR + d];
#pragma unroll
            for (int j = 0; j < 4; j++) bb[j] = Ks[(tx * 4 + j) * SSTR + d];
#pragma unroll
            for (int i = 0; i < 4; i++)
#pragma unroll
                for (int j = 0; j < 4; j++)
                    s[i][j] += a[i] * bb[j];
        }

        // scale (1/sqrt(64) = 0.125) + causal mask
        const int rbase = qt * BR + ty * 4;
        const int cbase = t * BC + tx * 4;
#pragma unroll
        for (int i = 0; i < 4; i++)
#pragma unroll
            for (int j = 0; j < 4; j++) {
                float sv = s[i][j] * 0.125f;
                if (cbase + j > rbase + i) sv = -1e30f;
                s[i][j] = sv;
            }

        // Online softmax per row (16 lanes share a row; xor-shuffle reduce)
#pragma unroll
        for (int i = 0; i < 4; i++) {
            float mx = s[i][0];
#pragma unroll
            for (int j = 1; j < 4; j++) mx = fmaxf(mx, s[i][j]);
#pragma unroll
            for (int off = 1; off < 16; off <<= 1)
                mx = fmaxf(mx, __shfl_xor_sync(0xffffffffu, mx, off));

            float mnew = fmaxf(m_i[i], mx);
            float corr = exp2f((m_i[i] - mnew) * LOG2E);

            float p[4];
            float psum = 0.0f;
#pragma unroll
            for (int j = 0; j < 4; j++) {
                p[j] = exp2f((s[i][j] - mnew) * LOG2E);
                psum += p[j];
            }
#pragma unroll
            for (int off = 1; off < 16; off <<= 1)
                psum += __shfl_xor_sync(0xffffffffu, psum, off);

            l_i[i] = l_i[i] * corr + psum;
            m_i[i] = mnew;
#pragma unroll
            for (int j = 0; j < 4; j++) o[i][j] *= corr;
#pragma unroll
            for (int j = 0; j < 4; j++)
                Ps[(ty * 4 + i) * SSTR + tx * 4 + j] = p[j];
        }
        __syncthreads();

        // O += P V   (per-thread 4 rows x 4 d-cols)
#pragma unroll 8
        for (int c = 0; c < BC; c++) {
            float pv[4], vv[4];
#pragma unroll
            for (int i = 0; i < 4; i++) pv[i] = Ps[(ty * 4 + i) * SSTR + c];
#pragma unroll
            for (int j = 0; j < 4; j++) vv[j] = Vs[c * SSTR + tx * 4 + j];
#pragma unroll
            for (int i = 0; i < 4; i++)
#pragma unroll
                for (int j = 0; j < 4; j++)
                    o[i][j] += pv[i] * vv[j];
        }
    }

    // Normalize and write ctx [b, s, h, d]
#pragma unroll
    for (int i = 0; i < 4; i++) {
        float inv = 1.0f / l_i[i];
        size_t row = (size_t)b * SEQ + qt * BR + ty * 4 + i;
#pragma unroll
        for (int j = 0; j < 4; j++) {
            CTX[row * DATTN + h * HD + tx * 4 + j] = o[i][j] * inv;
        }
    }
}

// ---------------------------------------------------------------------------
// Launch
// ---------------------------------------------------------------------------
extern "C" void kernel_launch(void* const* d_in, const int* in_sizes, int n_in,
                              void* d_out, int out_size)
{
    const float* x  = (const float*)d_in[0];
    const float* Wq = (const float*)d_in[1];
    const float* Wk = (const float*)d_in[2];
    const float* Wv = (const float*)d_in[3];
    const float* Wo = (const float*)d_in[4];
    const float* bo = (const float*)d_in[5];
    float* out = (float*)d_out;

    float *q, *k, *v, *ctx;
    cudaGetSymbolAddress((void**)&q,   g_q);
    cudaGetSymbolAddress((void**)&k,   g_k);
    cudaGetSymbolAddress((void**)&v,   g_v);
    cudaGetSymbolAddress((void**)&ctx, g_ctx);

    dim3 gB(DATTN / 128, MROWS / 128);  // (8, 32)

    // QKV projections
    sgemm_nt<<<gB, 256>>>(x, Wq, nullptr, q, MROWS, DATTN, DEMB);
    sgemm_nt<<<gB, 256>>>(x, Wk, nullptr, k, MROWS, DATTN, DEMB);
    sgemm_nt<<<gB, 256>>>(x, Wv, nullptr, v, MROWS, DATTN, DEMB);

    // Attention
    const int smem_att = 4 * BR * SSTR * (int)sizeof(float);  // 66560 B
    cudaFuncSetAttribute(attn_kernel, cudaFuncAttributeMaxDynamicSharedMemorySize,
                         smem_att);
    attn_kernel<<<dim3(SEQ / BR, NH, BS), 256, smem_att>>>(q, k, v, ctx);

    // Output projection + bias
    sgemm_nt<<<gB, 256>>>(ctx, Wo, bo, out, MROWS, DATTN, DATTN);
}

// round 3
// speedup vs baseline: 1.7084x; 1.7084x over previous
#include <cuda_runtime.h>
#include <cuda_bf16.h>
#include <cstdint>
#include <math.h>

#define BS    2
#define SEQ   2048
#define DEMB  1024
#define DATTN 1024
#define NH    16
#define HD    64
#define MROWS (BS*SEQ)   // 4096

#define LOG2E 1.4426950408889634f

// ---------------------------------------------------------------------------
// Scratch (device globals -- no allocation allowed)
// ---------------------------------------------------------------------------
__device__ float g_q[MROWS * DATTN];
__device__ float g_k[MROWS * DATTN];
__device__ float g_v[MROWS * DATTN];
__device__ float g_ctx[MROWS * DATTN];

__device__ __nv_bfloat16 g_xh[MROWS * DEMB];
__device__ __nv_bfloat16 g_xl[MROWS * DEMB];
__device__ __nv_bfloat16 g_wqh[DATTN * DEMB];
__device__ __nv_bfloat16 g_wql[DATTN * DEMB];
__device__ __nv_bfloat16 g_wkh[DATTN * DEMB];
__device__ __nv_bfloat16 g_wkl[DATTN * DEMB];
__device__ __nv_bfloat16 g_wvh[DATTN * DEMB];
__device__ __nv_bfloat16 g_wvl[DATTN * DEMB];
__device__ __nv_bfloat16 g_woh[DATTN * DATTN];
__device__ __nv_bfloat16 g_wol[DATTN * DATTN];
__device__ __nv_bfloat16 g_ch[MROWS * DATTN];
__device__ __nv_bfloat16 g_cl[MROWS * DATTN];

// ---------------------------------------------------------------------------
// PTX helpers (sm_100 baseline: HMMA mma.sync + ldmatrix + cp.async)
// ---------------------------------------------------------------------------
__device__ __forceinline__ uint32_t smem_u32(const void* p) {
    uint32_t a;
    asm("{ .reg .u64 t; cvta.to.shared.u64 t, %1; cvt.u32.u64 %0, t; }"
        : "=r"(a) : "l"(p));
    return a;
}

#define LDMATRIX_X4(r0, r1, r2, r3, addr) \
    asm volatile("ldmatrix.sync.aligned.m8n8.x4.shared.b16 {%0,%1,%2,%3}, [%4];" \
        : "=r"(r0), "=r"(r1), "=r"(r2), "=r"(r3) : "r"(addr))

#define MMA_BF16(d, a, b) \
    asm volatile("mma.sync.aligned.m16n8k16.row.col.f32.bf16.bf16.f32 " \
        "{%0,%1,%2,%3}, {%4,%5,%6,%7}, {%8,%9}, {%0,%1,%2,%3};" \
        : "+f"((d)[0]), "+f"((d)[1]), "+f"((d)[2]), "+f"((d)[3]) \
        : "r"((a)[0]), "r"((a)[1]), "r"((a)[2]), "r"((a)[3]), \
          "r"((b)[0]), "r"((b)[1]))

#define CP_ASYNC16(saddr, gptr) \
    asm volatile("cp.async.cg.shared.global [%0], [%1], 16;" \
        :: "r"(saddr), "l"(gptr))
#define CP_COMMIT() asm volatile("cp.async.commit_group;" ::: "memory")
#define CP_WAIT(n)  asm volatile("cp.async.wait_group %0;" :: "n"(n) : "memory")

__device__ __forceinline__ uint32_t sw128(uint32_t bo) {
    return bo ^ ((bo >> 3) & 0x70);
}

// ---------------------------------------------------------------------------
// fp32 -> (bf16 hi, bf16 lo) split
// ---------------------------------------------------------------------------
__global__ __launch_bounds__(256) void split_bf16(const float* __restrict__ src,
                                                  __nv_bfloat16* __restrict__ hi,
                                                  __nv_bfloat16* __restrict__ lo,
                                                  int n)
{
    int i = (blockIdx.x * blockDim.x + threadIdx.x) * 4;
    if (i >= n) return;
    float4 v = *(const float4*)(src + i);
    __nv_bfloat16 h0 = __float2bfloat16(v.x);
    __nv_bfloat16 h1 = __float2bfloat16(v.y);
    __nv_bfloat16 h2 = __float2bfloat16(v.z);
    __nv_bfloat16 h3 = __float2bfloat16(v.w);
    __nv_bfloat16 l0 = __float2bfloat16(v.x - __bfloat162float(h0));
    __nv_bfloat16 l1 = __float2bfloat16(v.y - __bfloat162float(h1));
    __nv_bfloat16 l2 = __float2bfloat16(v.z - __bfloat162float(h2));
    __nv_bfloat16 l3 = __float2bfloat16(v.w - __bfloat162float(h3));
    *(__nv_bfloat162*)(hi + i)     = __nv_bfloat162(h0, h1);
    *(__nv_bfloat162*)(hi + i + 2) = __nv_bfloat162(h2, h3);
    *(__nv_bfloat162*)(lo + i)     = __nv_bfloat162(l0, l1);
    *(__nv_bfloat162*)(lo + i + 2) = __nv_bfloat162(l2, l3);
}

// ---------------------------------------------------------------------------
// HMMA split-bf16 GEMM:  C[m,n] = sum_k A[m,k]*B[n,k]  (+ bias[n])
// CTA tile 128x128, BK=64 bf16, double-buffered cp.async.
// 8 warps (2x4): warp tile 64x32 = 4x4 m16n8k16 fragments.
// blockIdx.z selects (B, bias, C) -- QKV fused into one launch.
// ---------------------------------------------------------------------------
#define GK 1024   // fixed K for both gemms here
#define NKT (GK / 64)

__global__ __launch_bounds__(256, 1) void gemm_hmma(
    const __nv_bfloat16* __restrict__ Ah, const __nv_bfloat16* __restrict__ Al,
    const __nv_bfloat16* __restrict__ Bh0, const __nv_bfloat16* __restrict__ Bl0,
    const __nv_bfloat16* __restrict__ Bh1, const __nv_bfloat16* __restrict__ Bl1,
    const __nv_bfloat16* __restrict__ Bh2, const __nv_bfloat16* __restrict__ Bl2,
    const float* __restrict__ bias,
    float* __restrict__ C0, float* __restrict__ C1, float* __restrict__ C2,
    int N)
{
    extern __shared__ char smem[];
    const uint32_t sbase = smem_u32(smem);

    const int z = blockIdx.z;
    const __nv_bfloat16* Bh = (z == 0) ? Bh0 : (z == 1) ? Bh1 : Bh2;
    const __nv_bfloat16* Bl = (z == 0) ? Bl0 : (z == 1) ? Bl1 : Bl2;
    float* C = (z == 0) ? C0 : (z == 1) ? C1 : C2;

    const int tid = threadIdx.x;
    const int wid = tid >> 5;
    const int lid = tid & 31;
    const int warp_m = wid >> 2;      // 0..1
    const int warp_n = wid & 3;       // 0..3

    const int m0 = blockIdx.y * 128;
    const int n0 = blockIdx.x * 128;

    // Stage layout: [AH 16K][AL 16K][BH 16K][BL 16K] x 2 stages
    const uint32_t STG = 65536;

    // Per-thread load slots: 4 chunks of 16B per tile (1024 chunks / 256 thr)
    // chunk idx = it*256+tid -> r = idx>>3 (row 0..127), c = idx&7 (16B col)
    auto load_stage = [&](int kt, int s) {
        const uint32_t so = s * STG;
#pragma unroll
        for (int it = 0; it < 4; it++) {
            int idx = it * 256 + tid;
            int r   = idx >> 3;
            int c   = idx & 7;
            uint32_t sw = sw128((uint32_t)(r * 128 + c * 16));
            size_t ea = (size_t)(m0 + r) * GK + kt * 64 + c * 8;
            size_t eb = (size_t)(n0 + r) * GK + kt * 64 + c * 8;
            CP_ASYNC16(sbase + so + sw,          Ah + ea);
            CP_ASYNC16(sbase + so + 16384 + sw,  Al + ea);
            CP_ASYNC16(sbase + so + 32768 + sw,  Bh + eb);
            CP_ASYNC16(sbase + so + 49152 + sw,  Bl + eb);
        }
    };

    float acc[4][4][4];
#pragma unroll
    for (int i = 0; i < 4; i++)
#pragma unroll
        for (int j = 0; j < 4; j++)
#pragma unroll
            for (int r = 0; r < 4; r++) acc[i][j][r] = 0.0f;

    // ldmatrix thread addresses (within a stage/tile)
    // A: row = warp_m*64 + i*16 + (lid&15), colbyte = ks*32 + (lid>>4)*16
    const uint32_t a_row = warp_m * 64 + (lid & 15);
    const uint32_t a_cb  = (lid >> 4) * 16;
    // B: matrix idx = lid>>3; n_off = (mi>>1)*8 + (lid&7); kbyte = (mi&1)*16
    const uint32_t b_mi  = lid >> 3;
    const uint32_t b_row = warp_n * 32 + (b_mi >> 1) * 8 + (lid & 7);
    const uint32_t b_cb  = (b_mi & 1) * 16;

    load_stage(0, 0);
    CP_COMMIT();

    for (int kt = 0; kt < NKT; kt++) {
        if (kt + 1 < NKT) {
            load_stage(kt + 1, (kt + 1) & 1);
            CP_COMMIT();
            CP_WAIT(1);
        } else {
            CP_WAIT(0);
        }
        __syncthreads();

        const uint32_t so = (kt & 1) * STG;
        const uint32_t pAH = sbase + so;
        const uint32_t pAL = pAH + 16384;
        const uint32_t pBH = pAH + 32768;
        const uint32_t pBL = pAH + 49152;

#pragma unroll
        for (int ks = 0; ks < 4; ks++) {
            uint32_t ah[4][4], al[4][4], bh[4][2], bl[4][2];
#pragma unroll
            for (int i = 0; i < 4; i++) {
                uint32_t off = sw128((a_row + i * 16) * 128 + ks * 32 + a_cb);
                LDMATRIX_X4(ah[i][0], ah[i][1], ah[i][2], ah[i][3], pAH + off);
                LDMATRIX_X4(al[i][0], al[i][1], al[i][2], al[i][3], pAL + off);
            }
#pragma unroll
            for (int j2 = 0; j2 < 2; j2++) {
                uint32_t off = sw128((b_row + j2 * 16) * 128 + ks * 32 + b_cb);
                uint32_t r0, r1, r2, r3;
                LDMATRIX_X4(r0, r1, r2, r3, pBH + off);
                bh[j2*2][0] = r0; bh[j2*2][1] = r1;
                bh[j2*2+1][0] = r2; bh[j2*2+1][1] = r3;
                LDMATRIX_X4(r0, r1, r2, r3, pBL + off);
                bl[j2*2][0] = r0; bl[j2*2][1] = r1;
                bl[j2*2+1][0] = r2; bl[j2*2+1][1] = r3;
            }
#pragma unroll
            for (int i = 0; i < 4; i++)
#pragma unroll
                for (int j = 0; j < 4; j++) {
                    MMA_BF16(acc[i][j], ah[i], bh[j]);
                    MMA_BF16(acc[i][j], ah[i], bl[j]);
                    MMA_BF16(acc[i][j], al[i], bh[j]);
                }
        }
        __syncthreads();   // all warps done reading before stage is overwritten
    }

    // Epilogue: frags -> smem staging (stride 132) -> coalesced gmem + bias
    float* Cs = (float*)smem;
    const int gi = lid >> 2;        // group id: row within m16
    const int ti = lid & 3;         // thread in group: col pair
#pragma unroll
    for (int i = 0; i < 4; i++)
#pragma unroll
        for (int j = 0; j < 4; j++) {
            int row = warp_m * 64 + i * 16 + gi;
            int col = warp_n * 32 + j * 8 + ti * 2;
            Cs[row * 132 + col]           = acc[i][j][0];
            Cs[row * 132 + col + 1]       = acc[i][j][1];
            Cs[(row + 8) * 132 + col]     = acc[i][j][2];
            Cs[(row + 8) * 132 + col + 1] = acc[i][j][3];
        }
    __syncthreads();

#pragma unroll
    for (int it = 0; it < 16; it++) {
        int idx = it * 256 + tid;   // 0..4095
        int r   = idx >> 5;         // 0..127
        int c4  = (idx & 31) * 4;
        float4 v = *(float4*)(Cs + r * 132 + c4);
        if (bias && z == 0) {       // bias only used on the O-proj launch (z=0)
            float4 bv = *(const float4*)(bias + n0 + c4);
            v.x += bv.x; v.y += bv.y; v.z += bv.z; v.w += bv.w;
        }
        *(float4*)(C + (size_t)(m0 + r) * N + n0 + c4) = v;
    }
}

// ---------------------------------------------------------------------------
// Causal flash attention, fp32 (unchanged)
// ---------------------------------------------------------------------------
#define BR   64
#define BC   64
#define SSTR 65

extern __shared__ float sm_att[];

__global__ __launch_bounds__(256) void attn_kernel(const float* __restrict__ Q,
                                                   const float* __restrict__ K,
                                                   const float* __restrict__ V,
                                                   float* __restrict__ CTX)
{
    float* Qs = sm_att;
    float* Ks = Qs + BR * SSTR;
    float* Vs = Ks + BC * SSTR;
    float* Ps = Vs + BC * SSTR;

    const int qt = blockIdx.x;
    const int h  = blockIdx.y;
    const int b  = blockIdx.z;

    const int tid = threadIdx.x;
    const int tx  = tid & 15;
    const int ty  = tid >> 4;

    const float* Qh = Q + (size_t)b * SEQ * DATTN + h * HD;
    const float* Kh = K + (size_t)b * SEQ * DATTN + h * HD;
    const float* Vh = V + (size_t)b * SEQ * DATTN + h * HD;

#pragma unroll
    for (int it = 0; it < 4; it++) {
        int idx = it * 256 + tid;
        int r   = idx >> 4;
        int c4  = (idx & 15) * 4;
        float4 v = *(const float4*)(Qh + (size_t)(qt * BR + r) * DATTN + c4);
        Qs[r * SSTR + c4 + 0] = v.x;
        Qs[r * SSTR + c4 + 1] = v.y;
        Qs[r * SSTR + c4 + 2] = v.z;
        Qs[r * SSTR + c4 + 3] = v.w;
    }

    float m_i[4], l_i[4], o[4][4];
#pragma unroll
    for (int i = 0; i < 4; i++) {
        m_i[i] = -1e30f;
        l_i[i] = 0.0f;
#pragma unroll
        for (int j = 0; j < 4; j++) o[i][j] = 0.0f;
    }

    for (int t = 0; t <= qt; t++) {
        __syncthreads();
#pragma unroll
        for (int it = 0; it < 4; it++) {
            int idx = it * 256 + tid;
            int r   = idx >> 4;
            int c4  = (idx & 15) * 4;
            float4 kv = *(const float4*)(Kh + (size_t)(t * BC + r) * DATTN + c4);
            Ks[r * SSTR + c4 + 0] = kv.x;
            Ks[r * SSTR + c4 + 1] = kv.y;
            Ks[r * SSTR + c4 + 2] = kv.z;
            Ks[r * SSTR + c4 + 3] = kv.w;
            float4 vv = *(const float4*)(Vh + (size_t)(t * BC + r) * DATTN + c4);
            Vs[r * SSTR + c4 + 0] = vv.x;
            Vs[r * SSTR + c4 + 1] = vv.y;
            Vs[r * SSTR + c4 + 2] = vv.z;
            Vs[r * SSTR + c4 + 3] = vv.w;
        }
        __syncthreads();

        float s[4][4];
#pragma unroll
        for (int i = 0; i < 4; i++)
#pragma unroll
            for (int j = 0; j < 4; j++) s[i][j] = 0.0f;

#pragma unroll 8
        for (int d = 0; d < HD; d++) {
            float a[4], bb[4];
#pragma unroll
            for (int i = 0; i < 4; i++) a[i]  = Qs[(ty * 4 + i) * SSTR + d];
#pragma unroll
            for (int j = 0; j < 4; j++) bb[j] = Ks[(tx * 4 + j) * SSTR + d];
#pragma unroll
            for (int i = 0; i < 4; i++)
#pragma unroll
                for (int j = 0; j < 4; j++)
                    s[i][j] += a[i] * bb[j];
        }

        const int rbase = qt * BR + ty * 4;
        const int cbase = t * BC + tx * 4;
#pragma unroll
        for (int i = 0; i < 4; i++)
#pragma unroll
            for (int j = 0; j < 4; j++) {
                float sv = s[i][j] * 0.125f;
                if (cbase + j > rbase + i) sv = -1e30f;
                s[i][j] = sv;
            }

#pragma unroll
        for (int i = 0; i < 4; i++) {
            float mx = s[i][0];
#pragma unroll
            for (int j = 1; j < 4; j++) mx = fmaxf(mx, s[i][j]);
#pragma unroll
            for (int off = 1; off < 16; off <<= 1)
                mx = fmaxf(mx, __shfl_xor_sync(0xffffffffu, mx, off));

            float mnew = fmaxf(m_i[i], mx);
            float corr = exp2f((m_i[i] - mnew) * LOG2E);

            float p[4];
            float psum = 0.0f;
#pragma unroll
            for (int j = 0; j < 4; j++) {
                p[j] = exp2f((s[i][j] - mnew) * LOG2E);
                psum += p[j];
            }
#pragma unroll
            for (int off = 1; off < 16; off <<= 1)
                psum += __shfl_xor_sync(0xffffffffu, psum, off);

            l_i[i] = l_i[i] * corr + psum;
            m_i[i] = mnew;
#pragma unroll
            for (int j = 0; j < 4; j++) o[i][j] *= corr;
#pragma unroll
            for (int j = 0; j < 4; j++)
                Ps[(ty * 4 + i) * SSTR + tx * 4 + j] = p[j];
        }
        __syncthreads();

#pragma unroll 8
        for (int c = 0; c < BC; c++) {
            float pv[4], vv[4];
#pragma unroll
            for (int i = 0; i < 4; i++) pv[i] = Ps[(ty * 4 + i) * SSTR + c];
#pragma unroll
            for (int j = 0; j < 4; j++) vv[j] = Vs[c * SSTR + tx * 4 + j];
#pragma unroll
            for (int i = 0; i < 4; i++)
#pragma unroll
                for (int j = 0; j < 4; j++)
                    o[i][j] += pv[i] * vv[j];
        }
    }

#pragma unroll
    for (int i = 0; i < 4; i++) {
        float inv = 1.0f / l_i[i];
        size_t row = (size_t)b * SEQ + qt * BR + ty * 4 + i;
#pragma unroll
        for (int j = 0; j < 4; j++) {
            CTX[row * DATTN + h * HD + tx * 4 + j] = o[i][j] * inv;
        }
    }
}

// ---------------------------------------------------------------------------
// Launch
// ---------------------------------------------------------------------------
extern "C" void kernel_launch(void* const* d_in, const int* in_sizes, int n_in,
                              void* d_out, int out_size)
{
    const float* x  = (const float*)d_in[0];
    const float* Wq = (const float*)d_in[1];
    const float* Wk = (const float*)d_in[2];
    const float* Wv = (const float*)d_in[3];
    const float* Wo = (const float*)d_in[4];
    const float* bo = (const float*)d_in[5];
    float* out = (float*)d_out;

    float *q, *k, *v, *ctx;
    cudaGetSymbolAddress((void**)&q,   g_q);
    cudaGetSymbolAddress((void**)&k,   g_k);
    cudaGetSymbolAddress((void**)&v,   g_v);
    cudaGetSymbolAddress((void**)&ctx, g_ctx);

    __nv_bfloat16 *xh, *xl, *wqh, *wql, *wkh, *wkl, *wvh, *wvl, *woh, *wol, *ch, *cl;
    cudaGetSymbolAddress((void**)&xh,  g_xh);
    cudaGetSymbolAddress((void**)&xl,  g_xl);
    cudaGetSymbolAddress((void**)&wqh, g_wqh);
    cudaGetSymbolAddress((void**)&wql, g_wql);
    cudaGetSymbolAddress((void**)&wkh, g_wkh);
    cudaGetSymbolAddress((void**)&wkl, g_wkl);
    cudaGetSymbolAddress((void**)&wvh, g_wvh);
    cudaGetSymbolAddress((void**)&wvl, g_wvl);
    cudaGetSymbolAddress((void**)&woh, g_woh);
    cudaGetSymbolAddress((void**)&wol, g_wol);
    cudaGetSymbolAddress((void**)&ch,  g_ch);
    cudaGetSymbolAddress((void**)&cl,  g_cl);

    // bf16 splits
    const int NX = MROWS * DEMB;        // 4194304
    const int NW = DATTN * DEMB;        // 1048576
    split_bf16<<<NX / 1024, 256>>>(x,  xh,  xl,  NX);
    split_bf16<<<NW / 1024, 256>>>(Wq, wqh, wql, NW);
    split_bf16<<<NW / 1024, 256>>>(Wk, wkh, wkl, NW);
    split_bf16<<<NW / 1024, 256>>>(Wv, wvh, wvl, NW);
    split_bf16<<<NW / 1024, 256>>>(Wo, woh, wol, NW);

    const int smem_gemm = 131072;   // 2 stages x 64KB
    cudaFuncSetAttribute(gemm_hmma, cudaFuncAttributeMaxDynamicSharedMemorySize,
                         smem_gemm);

    // QKV fused (z selects weight/output)
    gemm_hmma<<<dim3(DATTN / 128, MROWS / 128, 3), 256, smem_gemm>>>(
        xh, xl, wqh, wql, wkh, wkl, wvh, wvl, nullptr, q, k, v, DATTN);

    // Attention
    const int smem_att = 4 * BR * SSTR * (int)sizeof(float);
    cudaFuncSetAttribute(attn_kernel, cudaFuncAttributeMaxDynamicSharedMemorySize,
                         smem_att);
    attn_kernel<<<dim3(SEQ / BR, NH, BS), 256, smem_att>>>(q, k, v, ctx);

    // ctx split + output projection (+bias) -- z=0 only
    split_bf16<<<NX / 1024, 256>>>(ctx, ch, cl, NX);
    gemm_hmma<<<dim3(DATTN / 128, MROWS / 128, 1), 256, smem_gemm>>>(
        ch, cl, woh, wol, nullptr, nullptr, nullptr, nullptr, bo, out, out, out, DATTN);
}

// round 4
// speedup vs baseline: 3.4609x; 2.0258x over previous
#include <cuda_runtime.h>
#include <cuda_bf16.h>
#include <cstdint>
#include <math.h>

#define BS    2
#define SEQ   2048
#define DEMB  1024
#define DATTN 1024
#define NH    16
#define HD    64
#define MROWS (BS*SEQ)   // 4096

#define LOG2E 1.4426950408889634f

// ---------------------------------------------------------------------------
// Scratch (device globals -- no allocation allowed)
// ---------------------------------------------------------------------------
__device__ __nv_bfloat16 g_xh[MROWS * DEMB];
__device__ __nv_bfloat16 g_xl[MROWS * DEMB];
__device__ __nv_bfloat16 g_wqh[DATTN * DEMB];
__device__ __nv_bfloat16 g_wql[DATTN * DEMB];
__device__ __nv_bfloat16 g_wkh[DATTN * DEMB];
__device__ __nv_bfloat16 g_wkl[DATTN * DEMB];
__device__ __nv_bfloat16 g_wvh[DATTN * DEMB];
__device__ __nv_bfloat16 g_wvl[DATTN * DEMB];
__device__ __nv_bfloat16 g_woh[DATTN * DATTN];
__device__ __nv_bfloat16 g_wol[DATTN * DATTN];
__device__ __nv_bfloat16 g_qh[MROWS * DATTN];
__device__ __nv_bfloat16 g_ql[MROWS * DATTN];
__device__ __nv_bfloat16 g_kh[MROWS * DATTN];
__device__ __nv_bfloat16 g_kl[MROWS * DATTN];
__device__ __nv_bfloat16 g_vh[MROWS * DATTN];
__device__ __nv_bfloat16 g_vl[MROWS * DATTN];
__device__ __nv_bfloat16 g_ch[MROWS * DATTN];
__device__ __nv_bfloat16 g_cl[MROWS * DATTN];

// ---------------------------------------------------------------------------
// PTX helpers
// ---------------------------------------------------------------------------
__device__ __forceinline__ uint32_t smem_u32(const void* p) {
    uint32_t a;
    asm("{ .reg .u64 t; cvta.to.shared.u64 t, %1; cvt.u32.u64 %0, t; }"
        : "=r"(a) : "l"(p));
    return a;
}

#define LDMATRIX_X4(r0, r1, r2, r3, addr) \
    asm volatile("ldmatrix.sync.aligned.m8n8.x4.shared.b16 {%0,%1,%2,%3}, [%4];" \
        : "=r"(r0), "=r"(r1), "=r"(r2), "=r"(r3) : "r"(addr))

#define LDMATRIX_X4T(r0, r1, r2, r3, addr) \
    asm volatile("ldmatrix.sync.aligned.m8n8.x4.trans.shared.b16 {%0,%1,%2,%3}, [%4];" \
        : "=r"(r0), "=r"(r1), "=r"(r2), "=r"(r3) : "r"(addr))

#define MMA_BF16(d, a, b) \
    asm volatile("mma.sync.aligned.m16n8k16.row.col.f32.bf16.bf16.f32 " \
        "{%0,%1,%2,%3}, {%4,%5,%6,%7}, {%8,%9}, {%0,%1,%2,%3};" \
        : "+f"((d)[0]), "+f"((d)[1]), "+f"((d)[2]), "+f"((d)[3]) \
        : "r"((a)[0]), "r"((a)[1]), "r"((a)[2]), "r"((a)[3]), \
          "r"((b)[0]), "r"((b)[1]))

#define CP_ASYNC16(saddr, gptr) \
    asm volatile("cp.async.cg.shared.global [%0], [%1], 16;" \
        :: "r"(saddr), "l"(gptr))
#define CP_COMMIT() asm volatile("cp.async.commit_group;" ::: "memory")
#define CP_WAIT(n)  asm volatile("cp.async.wait_group %0;" :: "n"(n) : "memory")

__device__ __forceinline__ uint32_t sw128(uint32_t bo) {
    return bo ^ ((bo >> 3) & 0x70);
}

// pack two floats into bf16x2 hi + residual lo
__device__ __forceinline__ void split2(float x, float y, uint32_t& hi, uint32_t& lo) {
    __nv_bfloat16 hx = __float2bfloat16(x), hy = __float2bfloat16(y);
    __nv_bfloat16 lx = __float2bfloat16(x - __bfloat162float(hx));
    __nv_bfloat16 ly = __float2bfloat16(y - __bfloat162float(hy));
    __nv_bfloat162 ph = __nv_bfloat162(hx, hy);
    __nv_bfloat162 pl = __nv_bfloat162(lx, ly);
    hi = *reinterpret_cast<uint32_t*>(&ph);
    lo = *reinterpret_cast<uint32_t*>(&pl);
}

// ---------------------------------------------------------------------------
// fp32 -> (bf16 hi, bf16 lo) split
// ---------------------------------------------------------------------------
__global__ __launch_bounds__(256) void split_bf16(const float* __restrict__ src,
                                                  __nv_bfloat16* __restrict__ hi,
                                                  __nv_bfloat16* __restrict__ lo,
                                                  int n)
{
    int i = (blockIdx.x * blockDim.x + threadIdx.x) * 4;
    if (i >= n) return;
    float4 v = *(const float4*)(src + i);
    uint32_t h01, l01, h23, l23;
    split2(v.x, v.y, h01, l01);
    split2(v.z, v.w, h23, l23);
    *(uint2*)(hi + i) = make_uint2(h01, h23);
    *(uint2*)(lo + i) = make_uint2(l01, l23);
}

// ---------------------------------------------------------------------------
// HMMA split-bf16 GEMM:  C[m,n] = sum_k A[m,k]*B[n,k]
// Output: either fp32 C (+bias) or split bf16 (H,L) when H != nullptr.
// CTA tile 128x128, BK=64, double-buffered cp.async; blockIdx.z selects set.
// ---------------------------------------------------------------------------
#define GK 1024
#define NKT (GK / 64)

__global__ __launch_bounds__(256, 1) void gemm_hmma(
    const __nv_bfloat16* __restrict__ Ah, const __nv_bfloat16* __restrict__ Al,
    const __nv_bfloat16* __restrict__ Bh0, const __nv_bfloat16* __restrict__ Bl0,
    const __nv_bfloat16* __restrict__ Bh1, const __nv_bfloat16* __restrict__ Bl1,
    const __nv_bfloat16* __restrict__ Bh2, const __nv_bfloat16* __restrict__ Bl2,
    const float* __restrict__ bias,
    float* __restrict__ Cf,
    __nv_bfloat16* __restrict__ H0, __nv_bfloat16* __restrict__ L0,
    __nv_bfloat16* __restrict__ H1, __nv_bfloat16* __restrict__ L1,
    __nv_bfloat16* __restrict__ H2, __nv_bfloat16* __restrict__ L2,
    int N)
{
    extern __shared__ char smem[];
    const uint32_t sbase = smem_u32(smem);

    const int z = blockIdx.z;
    const __nv_bfloat16* Bh = (z == 0) ? Bh0 : (z == 1) ? Bh1 : Bh2;
    const __nv_bfloat16* Bl = (z == 0) ? Bl0 : (z == 1) ? Bl1 : Bl2;
    __nv_bfloat16* Hs = (z == 0) ? H0 : (z == 1) ? H1 : H2;
    __nv_bfloat16* Ls = (z == 0) ? L0 : (z == 1) ? L1 : L2;

    const int tid = threadIdx.x;
    const int wid = tid >> 5;
    const int lid = tid & 31;
    const int warp_m = wid >> 2;
    const int warp_n = wid & 3;

    const int m0 = blockIdx.y * 128;
    const int n0 = blockIdx.x * 128;

    const uint32_t STG = 65536;

    auto load_stage = [&](int kt, int s) {
        const uint32_t so = s * STG;
#pragma unroll
        for (int it = 0; it < 4; it++) {
            int idx = it * 256 + tid;
            int r   = idx >> 3;
            int c   = idx & 7;
            uint32_t sw = sw128((uint32_t)(r * 128 + c * 16));
            size_t ea = (size_t)(m0 + r) * GK + kt * 64 + c * 8;
            size_t eb = (size_t)(n0 + r) * GK + kt * 64 + c * 8;
            CP_ASYNC16(sbase + so + sw,          Ah + ea);
            CP_ASYNC16(sbase + so + 16384 + sw,  Al + ea);
            CP_ASYNC16(sbase + so + 32768 + sw,  Bh + eb);
            CP_ASYNC16(sbase + so + 49152 + sw,  Bl + eb);
        }
    };

    float acc[4][4][4];
#pragma unroll
    for (int i = 0; i < 4; i++)
#pragma unroll
        for (int j = 0; j < 4; j++)
#pragma unroll
            for (int r = 0; r < 4; r++) acc[i][j][r] = 0.0f;

    const uint32_t a_row = warp_m * 64 + (lid & 15);
    const uint32_t a_cb  = (lid >> 4) * 16;
    const uint32_t b_mi  = lid >> 3;
    const uint32_t b_row = warp_n * 32 + (b_mi >> 1) * 8 + (lid & 7);
    const uint32_t b_cb  = (b_mi & 1) * 16;

    load_stage(0, 0);
    CP_COMMIT();

    for (int kt = 0; kt < NKT; kt++) {
        if (kt + 1 < NKT) {
            load_stage(kt + 1, (kt + 1) & 1);
            CP_COMMIT();
            CP_WAIT(1);
        } else {
            CP_WAIT(0);
        }
        __syncthreads();

        const uint32_t so = (kt & 1) * STG;
        const uint32_t pAH = sbase + so;
        const uint32_t pAL = pAH + 16384;
        const uint32_t pBH = pAH + 32768;
        const uint32_t pBL = pAH + 49152;

#pragma unroll
        for (int ks = 0; ks < 4; ks++) {
            uint32_t ah[4][4], al[4][4], bh[4][2], bl[4][2];
#pragma unroll
            for (int i = 0; i < 4; i++) {
                uint32_t off = sw128((a_row + i * 16) * 128 + ks * 32 + a_cb);
                LDMATRIX_X4(ah[i][0], ah[i][1], ah[i][2], ah[i][3], pAH + off);
                LDMATRIX_X4(al[i][0], al[i][1], al[i][2], al[i][3], pAL + off);
            }
#pragma unroll
            for (int j2 = 0; j2 < 2; j2++) {
                uint32_t off = sw128((b_row + j2 * 16) * 128 + ks * 32 + b_cb);
                uint32_t r0, r1, r2, r3;
                LDMATRIX_X4(r0, r1, r2, r3, pBH + off);
                bh[j2*2][0] = r0; bh[j2*2][1] = r1;
                bh[j2*2+1][0] = r2; bh[j2*2+1][1] = r3;
                LDMATRIX_X4(r0, r1, r2, r3, pBL + off);
                bl[j2*2][0] = r0; bl[j2*2][1] = r1;
                bl[j2*2+1][0] = r2; bl[j2*2+1][1] = r3;
            }
#pragma unroll
            for (int i = 0; i < 4; i++)
#pragma unroll
                for (int j = 0; j < 4; j++) {
                    MMA_BF16(acc[i][j], ah[i], bh[j]);
                    MMA_BF16(acc[i][j], ah[i], bl[j]);
                    MMA_BF16(acc[i][j], al[i], bh[j]);
                }
        }
        __syncthreads();
    }

    // Epilogue: frags -> smem staging -> coalesced out
    float* Cs = (float*)smem;
    const int gi = lid >> 2;
    const int ti = lid & 3;
#pragma unroll
    for (int i = 0; i < 4; i++)
#pragma unroll
        for (int j = 0; j < 4; j++) {
            int row = warp_m * 64 + i * 16 + gi;
            int col = warp_n * 32 + j * 8 + ti * 2;
            Cs[row * 132 + col]           = acc[i][j][0];
            Cs[row * 132 + col + 1]       = acc[i][j][1];
            Cs[(row + 8) * 132 + col]     = acc[i][j][2];
            Cs[(row + 8) * 132 + col + 1] = acc[i][j][3];
        }
    __syncthreads();

#pragma unroll
    for (int it = 0; it < 16; it++) {
        int idx = it * 256 + tid;
        int r   = idx >> 5;
        int c4  = (idx & 31) * 4;
        float4 v = *(float4*)(Cs + r * 132 + c4);
        size_t go = (size_t)(m0 + r) * N + n0 + c4;
        if (Hs) {
            uint32_t h01, l01, h23, l23;
            split2(v.x, v.y, h01, l01);
            split2(v.z, v.w, h23, l23);
            *(uint2*)(Hs + go) = make_uint2(h01, h23);
            *(uint2*)(Ls + go) = make_uint2(l01, l23);
        } else {
            if (bias) {
                float4 bv = *(const float4*)(bias + n0 + c4);
                v.x += bv.x; v.y += bv.y; v.z += bv.z; v.w += bv.w;
            }
            *(float4*)(Cf + go) = v;
        }
    }
}

// ---------------------------------------------------------------------------
// HMMA causal flash attention, split-bf16, Br=128, Bc=64, D=64.
// 8 warps; warp w owns Q rows w*16..w*16+15. Online softmax in registers.
// Inputs: pre-split bf16 hi/lo Q,K,V [row 0..4095][h*64+d].
// Output: split bf16 ctx (hi/lo).
// ---------------------------------------------------------------------------
__global__ __launch_bounds__(256, 1) void attn_hmma(
    const __nv_bfloat16* __restrict__ Qh, const __nv_bfloat16* __restrict__ Ql,
    const __nv_bfloat16* __restrict__ Kh, const __nv_bfloat16* __restrict__ Kl,
    const __nv_bfloat16* __restrict__ Vh, const __nv_bfloat16* __restrict__ Vl,
    __nv_bfloat16* __restrict__ Ch, __nv_bfloat16* __restrict__ Cl)
{
    extern __shared__ char smem[];
    const uint32_t sb = smem_u32(smem);
    const int tid = threadIdx.x, wid = tid >> 5, lid = tid & 31;
    const int gi = lid >> 2, ci = lid & 3;
    const int qt = gridDim.x - 1 - blockIdx.x;   // descending qt for balance
    const int h = blockIdx.y, b = blockIdx.z;

    const uint32_t QHo = 0, QLo = 16384, ST = 32768, STSZ = 32768;
    // stage layout: KH +0, KL +8192, VH +16384, VL +24576

    const size_t qbase = ((size_t)b * SEQ + (size_t)qt * 128) * DATTN + h * HD;

    // Q tiles (hi/lo), 128 rows x 128B
#pragma unroll
    for (int it = 0; it < 4; it++) {
        int idx = it * 256 + tid;
        int r = idx >> 3, c = idx & 7;
        uint32_t sw = sw128((uint32_t)(r * 128 + c * 16));
        size_t g = qbase + (size_t)r * DATTN + c * 8;
        CP_ASYNC16(sb + QHo + sw, Qh + g);
        CP_ASYNC16(sb + QLo + sw, Ql + g);
    }
    // stage 0 K/V
    {
        size_t kb = (size_t)b * SEQ * DATTN + h * HD;
#pragma unroll
        for (int it = 0; it < 2; it++) {
            int idx = it * 256 + tid;
            int r = idx >> 3, c = idx & 7;
            uint32_t sw = sw128((uint32_t)(r * 128 + c * 16));
            size_t g = kb + (size_t)r * DATTN + c * 8;
            CP_ASYNC16(sb + ST + sw,         Kh + g);
            CP_ASYNC16(sb + ST + 8192 + sw,  Kl + g);
            CP_ASYNC16(sb + ST + 16384 + sw, Vh + g);
            CP_ASYNC16(sb + ST + 24576 + sw, Vl + g);
        }
    }
    CP_COMMIT();

    float m_[2] = {-1e30f, -1e30f}, l_[2] = {0.f, 0.f};
    float oacc[8][4];
#pragma unroll
    for (int j = 0; j < 8; j++)
#pragma unroll
        for (int r = 0; r < 4; r++) oacc[j][r] = 0.0f;

    const int nkt = 2 * qt + 2;
    const uint32_t a_row = wid * 16 + (lid & 15);
    const uint32_t a_cb  = (lid >> 4) * 16;
    const int b_mi = lid >> 3;
    const uint32_t b_rl = (uint32_t)((b_mi >> 1) * 8 + (lid & 7));
    const uint32_t b_cb = (uint32_t)((b_mi & 1) * 16);
    const uint32_t v_key = (uint32_t)(lid & 15);
    const uint32_t v_cb  = (uint32_t)((lid >> 4) * 16);
    const int grow = qt * 128 + wid * 16 + gi;

    for (int kt = 0; kt < nkt; kt++) {
        if (kt + 1 < nkt) {
            uint32_t so = ST + ((kt + 1) & 1) * STSZ;
            size_t kb = ((size_t)b * SEQ + (size_t)(kt + 1) * 64) * DATTN + h * HD;
#pragma unroll
            for (int it = 0; it < 2; it++) {
                int idx = it * 256 + tid;
                int r = idx >> 3, c = idx & 7;
                uint32_t sw = sw128((uint32_t)(r * 128 + c * 16));
                size_t g = kb + (size_t)r * DATTN + c * 8;
                CP_ASYNC16(sb + so + sw,         Kh + g);
                CP_ASYNC16(sb + so + 8192 + sw,  Kl + g);
                CP_ASYNC16(sb + so + 16384 + sw, Vh + g);
                CP_ASYNC16(sb + so + 24576 + sw, Vl + g);
            }
            CP_COMMIT();
            CP_WAIT(1);
        } else {
            CP_WAIT(0);
        }
        __syncthreads();

        const uint32_t so = ST + (kt & 1) * STSZ;
        const uint32_t pKH = sb + so, pKL = pKH + 8192;
        const uint32_t pVH = pKH + 16384, pVL = pKH + 24576;

        // S = Q K^T (split 3-term)
        float sacc[8][4];
#pragma unroll
        for (int j = 0; j < 8; j++)
#pragma unroll
            for (int r = 0; r < 4; r++) sacc[j][r] = 0.0f;

#pragma unroll
        for (int ks = 0; ks < 4; ks++) {
            uint32_t qa[4], qb[4];
            uint32_t aoff = sw128(a_row * 128 + ks * 32 + a_cb);
            LDMATRIX_X4(qa[0], qa[1], qa[2], qa[3], sb + QHo + aoff);
            LDMATRIX_X4(qb[0], qb[1], qb[2], qb[3], sb + QLo + aoff);
#pragma unroll
            for (int j2 = 0; j2 < 4; j2++) {
                uint32_t boff = sw128((j2 * 16 + b_rl) * 128 + ks * 32 + b_cb);
                uint32_t h0, h1, h2, h3, l0, l1, l2, l3;
                LDMATRIX_X4(h0, h1, h2, h3, pKH + boff);
                LDMATRIX_X4(l0, l1, l2, l3, pKL + boff);
                uint32_t BH0[2] = {h0, h1}, BH1[2] = {h2, h3};
                uint32_t BL0[2] = {l0, l1}, BL1[2] = {l2, l3};
                MMA_BF16(sacc[2*j2],   qa, BH0);
                MMA_BF16(sacc[2*j2],   qa, BL0);
                MMA_BF16(sacc[2*j2],   qb, BH0);
                MMA_BF16(sacc[2*j2+1], qa, BH1);
                MMA_BF16(sacc[2*j2+1], qa, BL1);
                MMA_BF16(sacc[2*j2+1], qb, BH1);
            }
        }

        // scale + causal mask (boundary tiles only)
        const bool boundary = (kt >= 2 * qt);
#pragma unroll
        for (int j = 0; j < 8; j++)
#pragma unroll
            for (int r2 = 0; r2 < 2; r2++)
#pragma unroll
                for (int e = 0; e < 2; e++) {
                    float sv = sacc[j][r2 * 2 + e] * 0.125f;
                    if (boundary) {
                        int col = kt * 64 + j * 8 + 2 * ci + e;
                        if (col > grow + r2 * 8) sv = -1e30f;
                    }
                    sacc[j][r2 * 2 + e] = sv;
                }

        // row max (2 rows per lane; quad reduce)
        float mx0 = -1e30f, mx1 = -1e30f;
#pragma unroll
        for (int j = 0; j < 8; j++) {
            mx0 = fmaxf(mx0, fmaxf(sacc[j][0], sacc[j][1]));
            mx1 = fmaxf(mx1, fmaxf(sacc[j][2], sacc[j][3]));
        }
        mx0 = fmaxf(mx0, __shfl_xor_sync(0xffffffffu, mx0, 1));
        mx0 = fmaxf(mx0, __shfl_xor_sync(0xffffffffu, mx0, 2));
        mx1 = fmaxf(mx1, __shfl_xor_sync(0xffffffffu, mx1, 1));
        mx1 = fmaxf(mx1, __shfl_xor_sync(0xffffffffu, mx1, 2));

        const float mn0 = fmaxf(m_[0], mx0);
        const float mn1 = fmaxf(m_[1], mx1);
        const float co0 = exp2f((m_[0] - mn0) * LOG2E);
        const float co1 = exp2f((m_[1] - mn1) * LOG2E);

        float rs0 = 0.f, rs1 = 0.f;
#pragma unroll
        for (int j = 0; j < 8; j++) {
            float p0 = exp2f((sacc[j][0] - mn0) * LOG2E);
            float p1 = exp2f((sacc[j][1] - mn0) * LOG2E);
            float p2 = exp2f((sacc[j][2] - mn1) * LOG2E);
            float p3 = exp2f((sacc[j][3] - mn1) * LOG2E);
            rs0 += p0 + p1; rs1 += p2 + p3;
            sacc[j][0] = p0; sacc[j][1] = p1; sacc[j][2] = p2; sacc[j][3] = p3;
        }
        rs0 += __shfl_xor_sync(0xffffffffu, rs0, 1);
        rs0 += __shfl_xor_sync(0xffffffffu, rs0, 2);
        rs1 += __shfl_xor_sync(0xffffffffu, rs1, 1);
        rs1 += __shfl_xor_sync(0xffffffffu, rs1, 2);

        l_[0] = l_[0] * co0 + rs0;
        l_[1] = l_[1] * co1 + rs1;
        m_[0] = mn0; m_[1] = mn1;

#pragma unroll
        for (int jd = 0; jd < 8; jd++) {
            oacc[jd][0] *= co0; oacc[jd][1] *= co0;
            oacc[jd][2] *= co1; oacc[jd][3] *= co1;
        }

        // P -> split A-fragments (C-frag layout == A-frag layout)
        uint32_t ph[4][4], pl[4][4];
#pragma unroll
        for (int ks = 0; ks < 4; ks++) {
            int j0 = 2 * ks, j1 = 2 * ks + 1;
            split2(sacc[j0][0], sacc[j0][1], ph[ks][0], pl[ks][0]);
            split2(sacc[j0][2], sacc[j0][3], ph[ks][1], pl[ks][1]);
            split2(sacc[j1][0], sacc[j1][1], ph[ks][2], pl[ks][2]);
            split2(sacc[j1][2], sacc[j1][3], ph[ks][3], pl[ks][3]);
        }

        // O += P V  (V via ldmatrix.trans; split 3-term)
#pragma unroll
        for (int ks = 0; ks < 4; ks++) {
#pragma unroll
            for (int g = 0; g < 4; g++) {
                uint32_t voff = sw128((ks * 16 + v_key) * 128 + g * 32 + v_cb);
                uint32_t h0, h1, h2, h3, l0, l1, l2, l3;
                LDMATRIX_X4T(h0, h1, h2, h3, pVH + voff);
                LDMATRIX_X4T(l0, l1, l2, l3, pVL + voff);
                uint32_t VH0[2] = {h0, h1}, VH1[2] = {h2, h3};
                uint32_t VL0[2] = {l0, l1}, VL1[2] = {l2, l3};
                MMA_BF16(oacc[2*g],   ph[ks], VH0);
                MMA_BF16(oacc[2*g],   ph[ks], VL0);
                MMA_BF16(oacc[2*g],   pl[ks], VH0);
                MMA_BF16(oacc[2*g+1], ph[ks], VH1);
                MMA_BF16(oacc[2*g+1], ph[ks], VL1);
                MMA_BF16(oacc[2*g+1], pl[ks], VH1);
            }
        }
        __syncthreads();
    }

    // Epilogue: normalize, split, store ctx hi/lo
    const float inv0 = 1.0f / l_[0];
    const float inv1 = 1.0f / l_[1];
    const size_t ob0 = ((size_t)b * SEQ + grow) * DATTN + h * HD;
    const size_t ob1 = ob0 + (size_t)8 * DATTN;
#pragma unroll
    for (int jd = 0; jd < 8; jd++) {
        int col = jd * 8 + 2 * ci;
        uint32_t hv, lv;
        split2(oacc[jd][0] * inv0, oacc[jd][1] * inv0, hv, lv);
        *(uint32_t*)(Ch + ob0 + col) = hv;
        *(uint32_t*)(Cl + ob0 + col) = lv;
        split2(oacc[jd][2] * inv1, oacc[jd][3] * inv1, hv, lv);
        *(uint32_t*)(Ch + ob1 + col) = hv;
        *(uint32_t*)(Cl + ob1 + col) = lv;
    }
}

// ---------------------------------------------------------------------------
// Launch
// ---------------------------------------------------------------------------
extern "C" void kernel_launch(void* const* d_in, const int* in_sizes, int n_in,
                              void* d_out, int out_size)
{
    const float* x  = (const float*)d_in[0];
    const float* Wq = (const float*)d_in[1];
    const float* Wk = (const float*)d_in[2];
    const float* Wv = (const float*)d_in[3];
    const float* Wo = (const float*)d_in[4];
    const float* bo = (const float*)d_in[5];
    float* out = (float*)d_out;

    __nv_bfloat16 *xh, *xl, *wqh, *wql, *wkh, *wkl, *wvh, *wvl, *woh, *wol;
    __nv_bfloat16 *qh, *ql, *kh, *kl, *vh, *vl, *ch, *cl;
    cudaGetSymbolAddress((void**)&xh,  g_xh);
    cudaGetSymbolAddress((void**)&xl,  g_xl);
    cudaGetSymbolAddress((void**)&wqh, g_wqh);
    cudaGetSymbolAddress((void**)&wql, g_wql);
    cudaGetSymbolAddress((void**)&wkh, g_wkh);
    cudaGetSymbolAddress((void**)&wkl, g_wkl);
    cudaGetSymbolAddress((void**)&wvh, g_wvh);
    cudaGetSymbolAddress((void**)&wvl, g_wvl);
    cudaGetSymbolAddress((void**)&woh, g_woh);
    cudaGetSymbolAddress((void**)&wol, g_wol);
    cudaGetSymbolAddress((void**)&qh,  g_qh);
    cudaGetSymbolAddress((void**)&ql,  g_ql);
    cudaGetSymbolAddress((void**)&kh,  g_kh);
    cudaGetSymbolAddress((void**)&kl,  g_kl);
    cudaGetSymbolAddress((void**)&vh,  g_vh);
    cudaGetSymbolAddress((void**)&vl,  g_vl);
    cudaGetSymbolAddress((void**)&ch,  g_ch);
    cudaGetSymbolAddress((void**)&cl,  g_cl);

    const int NX = MROWS * DEMB;
    const int NW = DATTN * DEMB;
    split_bf16<<<NX / 1024, 256>>>(x,  xh,  xl,  NX);
    split_bf16<<<NW / 1024, 256>>>(Wq, wqh, wql, NW);
    split_bf16<<<NW / 1024, 256>>>(Wk, wkh, wkl, NW);
    split_bf16<<<NW / 1024, 256>>>(Wv, wvh, wvl, NW);
    split_bf16<<<NW / 1024, 256>>>(Wo, woh, wol, NW);

    const int smem_gemm = 131072;
    cudaFuncSetAttribute(gemm_hmma, cudaFuncAttributeMaxDynamicSharedMemorySize,
                         smem_gemm);

    // QKV fused; outputs split bf16 directly (no fp32 round trip)
    gemm_hmma<<<dim3(DATTN / 128, MROWS / 128, 3), 256, smem_gemm>>>(
        xh, xl, wqh, wql, wkh, wkl, wvh, wvl, nullptr, nullptr,
        qh, ql, kh, kl, vh, vl, DATTN);

    // Attention (outputs split ctx)
    const int smem_att = 98304;  // Q 32K + 2 stages x 32K
    cudaFuncSetAttribute(attn_hmma, cudaFuncAttributeMaxDynamicSharedMemorySize,
                         smem_att);
    attn_hmma<<<dim3(SEQ / 128, NH, BS), 256, smem_att>>>(
        qh, ql, kh, kl, vh, vl, ch, cl);

    // Output projection, fp32 + bias
    gemm_hmma<<<dim3(DATTN / 128, MROWS / 128, 1), 256, smem_gemm>>>(
        ch, cl, woh, wol, nullptr, nullptr, nullptr, nullptr, bo, out,
        nullptr, nullptr, nullptr, nullptr, nullptr, nullptr, DATTN);
}